// round 13
// baseline (speedup 1.0000x reference)
#include <cuda_runtime.h>
#include <cuda_bf16.h>

// DiracScheduler: fft_convolve(events, upsampled one-hot(argmax(pos))) ==
// per-row right-shift of events by d_e = argmax_e * 128, zero-filled head.
//
// Two kernels + PDL (programmatic dependent launch):
//   primary  : per-event argmax (64 blocks) -> g_delay[], triggers early launch
//   secondary: pure shifted copy (the measured-16.1us shape), launched with
//              ProgrammaticStreamSerialization; issues its delay-independent
//              ev loads, then cudaGridDependencySynchronize() before reading
//              g_delay. No per-block argmax, no barriers, no shuffles.
//
// pos:    [1, 64, 1024]   float32   (d_in[0])
// events: [2, 64, 131072] float32   (d_in[1])
// out:    [2, 64, 131072] float32

#define N_EVENTS   64
#define START_SIZE 1024
#define N_SAMPLES  131072
#define UPFACTOR   (N_SAMPLES / START_SIZE)   // 128 floats = 32 float4
#define BATCH      2
#define ROW_F4     (N_SAMPLES / 4)            // 32768 float4 per row
#define TPB        256

__device__ int g_delay[N_EVENTS];

// ---------------------------------------------------------------------------
// Primary: per-event argmax over 1024 positions -> delay (in float4 units).
// One block per event, 256 threads, first-occurrence tie-break (jnp.argmax).
// ---------------------------------------------------------------------------
__global__ void argmax_kernel(const float* __restrict__ pos) {
    __shared__ float s_val[8];
    __shared__ int   s_idx[8];

    const int e   = blockIdx.x;
    const int tid = threadIdx.x;
    const float* p = pos + e * START_SIZE;

    float mv = p[tid];
    int   mi = tid;
    #pragma unroll
    for (int k = 1; k < START_SIZE / TPB; ++k) {   // ascending idx, strict >
        int   idx = tid + k * TPB;
        float pv  = p[idx];
        if (pv > mv) { mv = pv; mi = idx; }
    }
    #pragma unroll
    for (int o = 16; o > 0; o >>= 1) {
        float ov = __shfl_down_sync(0xffffffff, mv, o);
        int   oi = __shfl_down_sync(0xffffffff, mi, o);
        if (ov > mv || (ov == mv && oi < mi)) { mv = ov; mi = oi; }
    }
    if ((tid & 31) == 0) { s_val[tid >> 5] = mv; s_idx[tid >> 5] = mi; }
    __syncthreads();
    if (tid < 32) {
        mv = (tid < 8) ? s_val[tid] : -3.402823466e+38f;
        mi = (tid < 8) ? s_idx[tid] : 0x7fffffff;
        #pragma unroll
        for (int o = 4; o > 0; o >>= 1) {
            float ov = __shfl_down_sync(0xffffffff, mv, o);
            int   oi = __shfl_down_sync(0xffffffff, mi, o);
            if (ov > mv || (ov == mv && oi < mi)) { mv = ov; mi = oi; }
        }
        if (tid == 0) g_delay[e] = mi * (UPFACTOR / 4);  // float4 units
    }
    // Allow the dependent (copy) kernel to begin launching now.
    cudaTriggerProgrammaticLaunchCompletion();
}

// ---------------------------------------------------------------------------
// Secondary: shifted copy, SCATTER form (load address delay-independent).
// 1 float4/thread, no smem reductions -> the 16-reg shape that hit 16.1us.
// grid = (ROW_F4/256, BATCH*N_EVENTS), block = 256.
// ---------------------------------------------------------------------------
__global__ void __launch_bounds__(TPB)
shift_kernel(const float4* __restrict__ ev, float4* __restrict__ out) {
    const int row = blockIdx.y;               // b*64 + e
    const int e   = row & (N_EVENTS - 1);
    const int t4  = blockIdx.x * TPB + threadIdx.x;
    const long base = (long)row * ROW_F4;

    // Delay-independent load, issued before we wait on the primary.
    float4 v = ev[base + t4];

    // Wait until the primary grid (argmax) has completed + flushed g_delay.
    cudaGridDependencySynchronize();

    const int d4 = g_delay[e];                // uniform broadcast load

    int dst = t4 + d4;
    if (dst >= ROW_F4) {                      // wraps into [0, d4): zero head
        dst -= ROW_F4;
        v = make_float4(0.f, 0.f, 0.f, 0.f);
    }
    out[base + dst] = v;                      // d4 mult of 32 f4 -> coalesced
}

extern "C" void kernel_launch(void* const* d_in, const int* in_sizes, int n_in,
                              void* d_out, int out_size) {
    const float*  pos = (const float*)d_in[0];
    const float4* ev  = (const float4*)d_in[1];
    float4*       out = (float4*)d_out;

    // Primary (normal launch).
    argmax_kernel<<<N_EVENTS, TPB>>>(pos);

    // Secondary with programmatic dependent launch: may begin while the
    // primary is still running; ordering enforced by griddepsync in-kernel.
    cudaLaunchAttribute attrs[1];
    attrs[0].id = cudaLaunchAttributeProgrammaticStreamSerialization;
    attrs[0].val.programmaticStreamSerializationAllowed = 1;

    cudaLaunchConfig_t cfg = {};
    cfg.gridDim  = dim3(ROW_F4 / TPB, BATCH * N_EVENTS);   // (128, 128)
    cfg.blockDim = dim3(TPB, 1, 1);
    cfg.dynamicSmemBytes = 0;
    cfg.stream = 0;
    cfg.attrs = attrs;
    cfg.numAttrs = 1;

    cudaLaunchKernelEx(&cfg, shift_kernel, ev, out);
}

// round 16
// speedup vs baseline: 1.1875x; 1.1875x over previous
#include <cuda_runtime.h>
#include <cuda_bf16.h>

// DiracScheduler: fft_convolve(events, upsampled one-hot(argmax(pos))) ==
// per-row right-shift of events by d_e = argmax_e * 128, zero-filled head.
//
// Two-kernel GATHER structure (best measured cache behavior: ~51MB DRAM
// traffic vs ~90MB for scatter forms). Copy kernel upgraded:
//   - 2 independent float4 loads per thread (MLP=2, latency hiding)
//   - __stcs evict-first streaming stores so `out` (write-once) doesn't
//     evict `events` (re-read every graph replay) from the 126MB L2.
// (Re-bench: previous run died to a container infra failure, not the kernel.)
//
// pos:    [1, 64, 1024]   float32   (d_in[0])
// events: [2, 64, 131072] float32   (d_in[1])
// out:    [2, 64, 131072] float32

#define N_EVENTS   64
#define START_SIZE 1024
#define N_SAMPLES  131072
#define UPFACTOR   (N_SAMPLES / START_SIZE)   // 128 floats = 32 float4
#define BATCH      2
#define ROW_F4     (N_SAMPLES / 4)            // 32768 float4 per row
#define TPB        256
#define VEC        2                          // float4 per thread
#define CHUNK_F4   (TPB * VEC)                // 512 f4 per block
#define BLK_PER_ROW (ROW_F4 / CHUNK_F4)       // 64

__device__ int g_delay[N_EVENTS];

// ---------------------------------------------------------------------------
// Kernel 1: per-event argmax over 1024 positions -> delay in float4 units.
// One block per event, 256 threads, first-occurrence tie-break (jnp.argmax).
// ---------------------------------------------------------------------------
__global__ void argmax_kernel(const float* __restrict__ pos) {
    __shared__ float s_val[8];
    __shared__ int   s_idx[8];

    const int e   = blockIdx.x;
    const int tid = threadIdx.x;
    const float* p = pos + e * START_SIZE;

    float mv = p[tid];
    int   mi = tid;
    #pragma unroll
    for (int k = 1; k < START_SIZE / TPB; ++k) {   // ascending idx, strict >
        int   idx = tid + k * TPB;
        float pv  = p[idx];
        if (pv > mv) { mv = pv; mi = idx; }
    }
    #pragma unroll
    for (int o = 16; o > 0; o >>= 1) {
        float ov = __shfl_down_sync(0xffffffff, mv, o);
        int   oi = __shfl_down_sync(0xffffffff, mi, o);
        if (ov > mv || (ov == mv && oi < mi)) { mv = ov; mi = oi; }
    }
    if ((tid & 31) == 0) { s_val[tid >> 5] = mv; s_idx[tid >> 5] = mi; }
    __syncthreads();
    if (tid < 32) {
        mv = (tid < 8) ? s_val[tid] : -3.402823466e+38f;
        mi = (tid < 8) ? s_idx[tid] : 0x7fffffff;
        #pragma unroll
        for (int o = 4; o > 0; o >>= 1) {
            float ov = __shfl_down_sync(0xffffffff, mv, o);
            int   oi = __shfl_down_sync(0xffffffff, mi, o);
            if (ov > mv || (ov == mv && oi < mi)) { mv = ov; mi = oi; }
        }
        if (tid == 0) g_delay[e] = mi * (UPFACTOR / 4);  // float4 units
    }
}

// ---------------------------------------------------------------------------
// Kernel 2: gather shifted copy, 2 float4/thread, streaming stores.
// grid = (BLK_PER_ROW, BATCH*N_EVENTS) = (64, 128), block = 256.
// ---------------------------------------------------------------------------
__global__ void __launch_bounds__(TPB)
shift_kernel(const float4* __restrict__ ev, float4* __restrict__ out) {
    const int row = blockIdx.y;               // b*64 + e
    const int e   = row & (N_EVENTS - 1);
    const int d4  = g_delay[e];               // uniform broadcast (L2-hot)

    const int t0  = blockIdx.x * CHUNK_F4 + threadIdx.x;
    const long base = (long)row * ROW_F4;

    // Two independent gathers (MLP=2). d4 is a multiple of 32 f4 -> both
    // loads and stores remain fully coalesced, alignment preserved.
    float4 v[VEC];
    #pragma unroll
    for (int k = 0; k < VEC; ++k) {
        const int t4  = t0 + k * TPB;
        const int src = t4 - d4;
        v[k] = (src >= 0) ? ev[base + src]
                          : make_float4(0.f, 0.f, 0.f, 0.f);
    }

    // Evict-first streaming stores: keep `events` resident in L2 across
    // graph replays instead of letting write-once `out` lines thrash it.
    #pragma unroll
    for (int k = 0; k < VEC; ++k)
        __stcs(&out[base + t0 + k * TPB], v[k]);
}

extern "C" void kernel_launch(void* const* d_in, const int* in_sizes, int n_in,
                              void* d_out, int out_size) {
    const float*  pos = (const float*)d_in[0];
    const float4* ev  = (const float4*)d_in[1];
    float4*       out = (float4*)d_out;

    argmax_kernel<<<N_EVENTS, TPB>>>(pos);

    dim3 grid(BLK_PER_ROW, BATCH * N_EVENTS);   // (64, 128)
    shift_kernel<<<grid, TPB>>>(ev, out);
}

// round 17
// speedup vs baseline: 1.4250x; 1.2000x over previous
#include <cuda_runtime.h>
#include <cuda_bf16.h>

// DiracScheduler: fft_convolve(events, upsampled one-hot(argmax(pos))) ==
// per-row right-shift of events by d_e = argmax_e * 128, zero-filled head.
//
// Two-kernel GATHER structure (R4, best measured). Single change vs R4:
// VEC=4 independent float4 gathers per thread (MLP=4) to push the
// latency-limited copy (R4: DRAM 40%, issue 31%, nothing saturated) toward
// the LSU/DRAM floor. Plain STG stores (the R16 __stcs experiment LOWERED
// DRAM throughput 40%->30% and is reverted).
//
// pos:    [1, 64, 1024]   float32   (d_in[0])
// events: [2, 64, 131072] float32   (d_in[1])
// out:    [2, 64, 131072] float32

#define N_EVENTS   64
#define START_SIZE 1024
#define N_SAMPLES  131072
#define UPFACTOR   (N_SAMPLES / START_SIZE)   // 128 floats = 32 float4
#define BATCH      2
#define ROW_F4     (N_SAMPLES / 4)            // 32768 float4 per row
#define TPB        256
#define VEC        4                          // float4 per thread (MLP=4)
#define CHUNK_F4   (TPB * VEC)                // 1024 f4 per block
#define BLK_PER_ROW (ROW_F4 / CHUNK_F4)       // 32

__device__ int g_delay[N_EVENTS];

// ---------------------------------------------------------------------------
// Kernel 1: per-event argmax over 1024 positions -> delay in float4 units.
// One block per event, 256 threads, first-occurrence tie-break (jnp.argmax).
// ---------------------------------------------------------------------------
__global__ void argmax_kernel(const float* __restrict__ pos) {
    __shared__ float s_val[8];
    __shared__ int   s_idx[8];

    const int e   = blockIdx.x;
    const int tid = threadIdx.x;
    const float* p = pos + e * START_SIZE;

    float mv = p[tid];
    int   mi = tid;
    #pragma unroll
    for (int k = 1; k < START_SIZE / TPB; ++k) {   // ascending idx, strict >
        int   idx = tid + k * TPB;
        float pv  = p[idx];
        if (pv > mv) { mv = pv; mi = idx; }
    }
    #pragma unroll
    for (int o = 16; o > 0; o >>= 1) {
        float ov = __shfl_down_sync(0xffffffff, mv, o);
        int   oi = __shfl_down_sync(0xffffffff, mi, o);
        if (ov > mv || (ov == mv && oi < mi)) { mv = ov; mi = oi; }
    }
    if ((tid & 31) == 0) { s_val[tid >> 5] = mv; s_idx[tid >> 5] = mi; }
    __syncthreads();
    if (tid < 32) {
        mv = (tid < 8) ? s_val[tid] : -3.402823466e+38f;
        mi = (tid < 8) ? s_idx[tid] : 0x7fffffff;
        #pragma unroll
        for (int o = 4; o > 0; o >>= 1) {
            float ov = __shfl_down_sync(0xffffffff, mv, o);
            int   oi = __shfl_down_sync(0xffffffff, mi, o);
            if (ov > mv || (ov == mv && oi < mi)) { mv = ov; mi = oi; }
        }
        if (tid == 0) g_delay[e] = mi * (UPFACTOR / 4);  // float4 units
    }
}

// ---------------------------------------------------------------------------
// Kernel 2: gather shifted copy, 4 independent float4 per thread, plain STG.
// grid = (BLK_PER_ROW, BATCH*N_EVENTS) = (32, 128), block = 256.
// ---------------------------------------------------------------------------
__global__ void __launch_bounds__(TPB)
shift_kernel(const float4* __restrict__ ev, float4* __restrict__ out) {
    const int row = blockIdx.y;               // b*64 + e
    const int e   = row & (N_EVENTS - 1);
    const int d4  = g_delay[e];               // uniform broadcast (L2-hot)

    const int t0  = blockIdx.x * CHUNK_F4 + threadIdx.x;
    const long base = (long)row * ROW_F4;

    // Four independent gathers (MLP=4), issued back-to-back. d4 is a
    // multiple of 32 f4 -> loads and stores stay fully coalesced & aligned.
    float4 v[VEC];
    #pragma unroll
    for (int k = 0; k < VEC; ++k) {
        const int src = t0 + k * TPB - d4;
        v[k] = (src >= 0) ? ev[base + src]
                          : make_float4(0.f, 0.f, 0.f, 0.f);
    }

    #pragma unroll
    for (int k = 0; k < VEC; ++k)
        out[base + t0 + k * TPB] = v[k];
}

extern "C" void kernel_launch(void* const* d_in, const int* in_sizes, int n_in,
                              void* d_out, int out_size) {
    const float*  pos = (const float*)d_in[0];
    const float4* ev  = (const float4*)d_in[1];
    float4*       out = (float4*)d_out;

    argmax_kernel<<<N_EVENTS, TPB>>>(pos);

    dim3 grid(BLK_PER_ROW, BATCH * N_EVENTS);   // (32, 128)
    shift_kernel<<<grid, TPB>>>(ev, out);
}